// round 3
// baseline (speedup 1.0000x reference)
#include <cuda_runtime.h>
#include <math.h>
#include <stdint.h>

#define NVOX 40000
#define NQ   8192
#define KK   96
#define C    128
#define FF   256
#define NH   8
#define DH   16

// ---------------- scratch (device globals; no allocation) ----------------
__device__ float g_kf[NVOX * C];        // LN(voxel_features)+key_pos, per voxel
__device__ float g_KV[NVOX * 2 * C];    // per-voxel [K(128) | V(128)]
__device__ float g_qfeat[NQ * C];
__device__ float g_q[NQ * C];
__device__ float g_ctx[NQ * C];
__device__ float g_att[NQ * C];
__device__ float g_hn[NQ * C];
__device__ float g_a1[NQ * FF];
__device__ float g_x[NQ * C];

// ---------------- kernel: per-voxel LN + positional feature ----------------
__global__ void kf_kernel(const float* __restrict__ vf,
                          const float* __restrict__ vc,
                          const float* __restrict__ g1,
                          const float* __restrict__ b1,
                          const float* __restrict__ kpw,
                          const float* __restrict__ kpb)
{
    int v    = blockIdx.x * 8 + (threadIdx.x >> 5);
    int lane = threadIdx.x & 31;
    if (v >= NVOX) return;

    float4 x = ((const float4*)(vf + (size_t)v * C))[lane];
    float s = x.x + x.y + x.z + x.w;
    float q = x.x * x.x + x.y * x.y + x.z * x.z + x.w * x.w;
#pragma unroll
    for (int o = 16; o; o >>= 1) {
        s += __shfl_xor_sync(0xffffffffu, s, o);
        q += __shfl_xor_sync(0xffffffffu, q, o);
    }
    float m   = s * (1.0f / 128.0f);
    float var = q * (1.0f / 128.0f) - m * m;
    float r   = rsqrtf(var + 1e-5f);

    float cx = vc[v * 3 + 0], cy = vc[v * 3 + 1], cz = vc[v * 3 + 2];

    float o0[4];
    const float* xv = &x.x;
#pragma unroll
    for (int j = 0; j < 4; j++) {
        int c = lane * 4 + j;
        float y  = (xv[j] - m) * r * g1[c] + b1[c];
        float kp = fmaxf(kpw[c * 3 + 0] * cx + kpw[c * 3 + 1] * cy +
                         kpw[c * 3 + 2] * cz + kpb[c], 0.0f);
        o0[j] = y + kp;
    }
    ((float4*)(g_kf + (size_t)v * C))[lane] = make_float4(o0[0], o0[1], o0[2], o0[3]);
}

// ---------------- kernel: row LayerNorm (norm2) ----------------
__global__ void ln_kernel(const float* __restrict__ in,
                          const float* __restrict__ g,
                          const float* __restrict__ b,
                          float* __restrict__ out, int rows)
{
    int r    = blockIdx.x * 8 + (threadIdx.x >> 5);
    int lane = threadIdx.x & 31;
    if (r >= rows) return;

    float4 x = ((const float4*)(in + (size_t)r * C))[lane];
    float s = x.x + x.y + x.z + x.w;
    float q = x.x * x.x + x.y * x.y + x.z * x.z + x.w * x.w;
#pragma unroll
    for (int o = 16; o; o >>= 1) {
        s += __shfl_xor_sync(0xffffffffu, s, o);
        q += __shfl_xor_sync(0xffffffffu, q, o);
    }
    float m   = s * (1.0f / 128.0f);
    float var = q * (1.0f / 128.0f) - m * m;
    float rs  = rsqrtf(var + 1e-5f);

    float o0[4];
    const float* xv = &x.x;
#pragma unroll
    for (int j = 0; j < 4; j++) {
        int c = lane * 4 + j;
        o0[j] = (xv[j] - m) * rs * g[c] + b[c];
    }
    ((float4*)(out + (size_t)r * C))[lane] = make_float4(o0[0], o0[1], o0[2], o0[3]);
}

// ---------------- kernel: q positional feature ----------------
__global__ void qfeat_kernel(const float* __restrict__ qc,
                             const float* __restrict__ qpw,
                             const float* __restrict__ qpb)
{
    int t = blockIdx.x * 256 + threadIdx.x;   // t < NQ*C
    int n = t >> 7, c = t & 127;
    float x = qc[n * 3 + 0], y = qc[n * 3 + 1], z = qc[n * 3 + 2];
    g_qfeat[t] = fmaxf(qpw[c * 3 + 0] * x + qpw[c * 3 + 1] * y +
                       qpw[c * 3 + 2] * z + qpb[c], 0.0f);
}

// ---------------- generic SGEMM:  out[M,N] = A[M,Kd] @ W[N,Kd]^T (+bias)(+res)(relu) ----------------
// 128x128 block tile, BK=8 double-buffered, 8x8 per-thread micro-tile, 256 threads.
__global__ __launch_bounds__(256, 2)
void sgemm_kernel(const float* __restrict__ A, int M,
                  const float* __restrict__ W,
                  const float* __restrict__ bias,
                  const float* __restrict__ res,
                  float* __restrict__ out,
                  int N, int Kd, int dorelu)
{
    __shared__ __align__(16) float As[2][8][132];
    __shared__ __align__(16) float Bs[2][8][132];

    const int tid  = threadIdx.x;
    const int m0   = blockIdx.x * 128;
    const int n0   = blockIdx.y * 128;
    const int warp = tid >> 5, lane = tid & 31;
    const int wm = warp >> 2, wn = warp & 3;   // 2 warps (m,64) x 4 warps (n,32)
    const int lm = lane & 7,  ln = lane >> 3;

    const int lrow = tid >> 1;        // 0..127
    const int lk4  = (tid & 1) * 4;   // 0 or 4

    const bool arow_ok = (m0 + lrow) < M;
    const float* Ap = A + (size_t)(m0 + lrow) * Kd + lk4;
    const float* Wp = W + (size_t)(n0 + lrow) * Kd + lk4;

    float acc[8][8];
#pragma unroll
    for (int i = 0; i < 8; i++)
#pragma unroll
        for (int j = 0; j < 8; j++) acc[i][j] = 0.0f;

    float4 a4 = arow_ok ? *(const float4*)Ap : make_float4(0, 0, 0, 0);
    float4 b4 = *(const float4*)Wp;

    int buf = 0;
    As[0][lk4 + 0][lrow] = a4.x; As[0][lk4 + 1][lrow] = a4.y;
    As[0][lk4 + 2][lrow] = a4.z; As[0][lk4 + 3][lrow] = a4.w;
    Bs[0][lk4 + 0][lrow] = b4.x; Bs[0][lk4 + 1][lrow] = b4.y;
    Bs[0][lk4 + 2][lrow] = b4.z; Bs[0][lk4 + 3][lrow] = b4.w;
    __syncthreads();

    for (int kc = 0; kc < Kd; kc += 8) {
        const bool more = (kc + 8) < Kd;
        if (more) {
            a4 = arow_ok ? *(const float4*)(Ap + kc + 8) : make_float4(0, 0, 0, 0);
            b4 = *(const float4*)(Wp + kc + 8);
        }
#pragma unroll
        for (int k = 0; k < 8; k++) {
            float4 t0 = *(const float4*)&As[buf][k][wm * 64 + lm * 4];
            float4 t1 = *(const float4*)&As[buf][k][wm * 64 + lm * 4 + 32];
            float4 u0 = *(const float4*)&Bs[buf][k][wn * 32 + ln * 4];
            float4 u1 = *(const float4*)&Bs[buf][k][wn * 32 + ln * 4 + 16];
            float af[8] = {t0.x, t0.y, t0.z, t0.w, t1.x, t1.y, t1.z, t1.w};
            float bf[8] = {u0.x, u0.y, u0.z, u0.w, u1.x, u1.y, u1.z, u1.w};
#pragma unroll
            for (int i = 0; i < 8; i++)
#pragma unroll
                for (int j = 0; j < 8; j++) acc[i][j] += af[i] * bf[j];
        }
        if (more) {
            int nb = buf ^ 1;
            As[nb][lk4 + 0][lrow] = a4.x; As[nb][lk4 + 1][lrow] = a4.y;
            As[nb][lk4 + 2][lrow] = a4.z; As[nb][lk4 + 3][lrow] = a4.w;
            Bs[nb][lk4 + 0][lrow] = b4.x; Bs[nb][lk4 + 1][lrow] = b4.y;
            Bs[nb][lk4 + 2][lrow] = b4.z; Bs[nb][lk4 + 3][lrow] = b4.w;
            __syncthreads();
            buf = nb;
        }
    }

    // epilogue
#pragma unroll
    for (int i = 0; i < 8; i++) {
        int mg = m0 + wm * 64 + lm * 4 + (i & 3) + ((i >> 2) * 32);
        if (mg >= M) continue;
#pragma unroll
        for (int j4 = 0; j4 < 2; j4++) {
            int ng = n0 + wn * 32 + ln * 4 + j4 * 16;
            float4 o;
            o.x = acc[i][j4 * 4 + 0] + bias[ng + 0];
            o.y = acc[i][j4 * 4 + 1] + bias[ng + 1];
            o.z = acc[i][j4 * 4 + 2] + bias[ng + 2];
            o.w = acc[i][j4 * 4 + 3] + bias[ng + 3];
            if (res) {
                float4 rr = *(const float4*)(res + (size_t)mg * N + ng);
                o.x += rr.x; o.y += rr.y; o.z += rr.z; o.w += rr.w;
            }
            if (dorelu) {
                o.x = fmaxf(o.x, 0.0f); o.y = fmaxf(o.y, 0.0f);
                o.z = fmaxf(o.z, 0.0f); o.w = fmaxf(o.w, 0.0f);
            }
            *(float4*)(out + (size_t)mg * N + ng) = o;
        }
    }
}

// ---------------- attention: one block per query, 128 threads ----------------
__global__ __launch_bounds__(128)
void attn_kernel(const int* __restrict__ kidx)
{
    __shared__ int   idx_s[KK];
    __shared__ float s_s[NH][KK];

    const int n = blockIdx.x;
    const int t = threadIdx.x;           // channel = t
    const int h = t >> 4, l16 = t & 15;  // head, lane-in-head

    if (t < KK) idx_s[t] = kidx[n * KK + t];
    const float qv = g_q[(size_t)n * C + t];
    __syncthreads();

    // phase 1: scores[h][k] = (q_h . K_h[idx]) * 1/sqrt(16)
#pragma unroll 4
    for (int k = 0; k < KK; k++) {
        int v = idx_s[k];
        if (v >= 0) {
            float val = qv * __ldg(&g_KV[(size_t)v * 256 + t]);
            val += __shfl_xor_sync(0xffffffffu, val, 8, 16);
            val += __shfl_xor_sync(0xffffffffu, val, 4, 16);
            val += __shfl_xor_sync(0xffffffffu, val, 2, 16);
            val += __shfl_xor_sync(0xffffffffu, val, 1, 16);
            if (l16 == 0) s_s[h][k] = val * 0.25f;
        }
    }
    __syncthreads();

    // phase 2: softmax over valid keys (head h handled by its own 16 lanes)
    float mx = -1e30f;
    for (int k = l16; k < KK; k += 16)
        if (idx_s[k] >= 0) mx = fmaxf(mx, s_s[h][k]);
#pragma unroll
    for (int o = 8; o; o >>= 1)
        mx = fmaxf(mx, __shfl_xor_sync(0xffffffffu, mx, o, 16));

    float sum = 0.0f;
    for (int k = l16; k < KK; k += 16) {
        float p = 0.0f;
        if (idx_s[k] >= 0) p = __expf(s_s[h][k] - mx);
        s_s[h][k] = p;
        sum += p;
    }
#pragma unroll
    for (int o = 8; o; o >>= 1)
        sum += __shfl_xor_sync(0xffffffffu, sum, o, 16);
    const float inv = 1.0f / sum;
    __syncthreads();

    // phase 3: ctx[c] = sum_k p[h][k] * V[idx[k]][c]
    float acc = 0.0f;
#pragma unroll 4
    for (int k = 0; k < KK; k++) {
        int v = idx_s[k];
        if (v >= 0)
            acc += s_s[h][k] * __ldg(&g_KV[(size_t)v * 256 + 128 + t]);
    }
    g_ctx[(size_t)n * C + t] = acc * inv;
}

// ---------------- host launch ----------------
extern "C" void kernel_launch(void* const* d_in, const int* in_sizes, int n_in,
                              void* d_out, int out_size)
{
    const float* vf   = (const float*)d_in[0];
    const float* vc   = (const float*)d_in[1];
    const float* qc   = (const float*)d_in[2];
    const int*   kidx = (const int*)  d_in[3];
    const float* n1g  = (const float*)d_in[4];
    const float* n1b  = (const float*)d_in[5];
    const float* qpw  = (const float*)d_in[6];
    const float* qpb  = (const float*)d_in[7];
    const float* kpw  = (const float*)d_in[8];
    const float* kpb  = (const float*)d_in[9];
    const float* inw  = (const float*)d_in[10];
    const float* inb  = (const float*)d_in[11];
    const float* outw = (const float*)d_in[12];
    const float* outb = (const float*)d_in[13];
    const float* n2g  = (const float*)d_in[14];
    const float* n2b  = (const float*)d_in[15];
    const float* l1w  = (const float*)d_in[16];
    const float* l1b  = (const float*)d_in[17];
    const float* l2w  = (const float*)d_in[18];
    const float* l2b  = (const float*)d_in[19];
    const float* fw   = (const float*)d_in[20];
    const float* fb   = (const float*)d_in[21];
    float* out = (float*)d_out;

    float *p_kf, *p_KV, *p_qf, *p_q, *p_ctx, *p_att, *p_hn, *p_a1, *p_x;
    cudaGetSymbolAddress((void**)&p_kf,  g_kf);
    cudaGetSymbolAddress((void**)&p_KV,  g_KV);
    cudaGetSymbolAddress((void**)&p_qf,  g_qfeat);
    cudaGetSymbolAddress((void**)&p_q,   g_q);
    cudaGetSymbolAddress((void**)&p_ctx, g_ctx);
    cudaGetSymbolAddress((void**)&p_att, g_att);
    cudaGetSymbolAddress((void**)&p_hn,  g_hn);
    cudaGetSymbolAddress((void**)&p_a1,  g_a1);
    cudaGetSymbolAddress((void**)&p_x,   g_x);

    // 1) per-voxel LN + key positional feature
    kf_kernel<<<NVOX / 8, 256>>>(vf, vc, n1g, n1b, kpw, kpb);

    // 2) per-voxel K|V projection: [NVOX,128] @ in_w[128:384]^T  -> [NVOX,256]
    sgemm_kernel<<<dim3((NVOX + 127) / 128, 2), 256>>>(
        p_kf, NVOX, inw + 128 * 128, inb + 128, nullptr, p_KV, 256, 128, 0);

    // 3) query positional feature
    qfeat_kernel<<<(NQ * C) / 256, 256>>>(qc, qpw, qpb);

    // 4) q projection
    sgemm_kernel<<<dim3(NQ / 128, 1), 256>>>(
        p_qf, NQ, inw, inb, nullptr, p_q, 128, 128, 0);

    // 5) sparse attention (gather K/V rows by voxel index)
    attn_kernel<<<NQ, 128>>>(kidx);

    // 6) output projection -> attend
    sgemm_kernel<<<dim3(NQ / 128, 1), 256>>>(
        p_ctx, NQ, outw, outb, nullptr, p_att, 128, 128, 0);

    // 7) norm2
    ln_kernel<<<NQ / 8, 256>>>(p_att, n2g, n2b, p_hn, NQ);

    // 8) FFN up (relu)
    sgemm_kernel<<<dim3(NQ / 128, 2), 256>>>(
        p_hn, NQ, l1w, l1b, nullptr, p_a1, 256, 128, 1);

    // 9) FFN down + residual(attend)
    sgemm_kernel<<<dim3(NQ / 128, 1), 256>>>(
        p_a1, NQ, l2w, l2b, p_att, p_x, 128, 256, 0);

    // 10) final projection + relu -> output
    sgemm_kernel<<<dim3(NQ / 128, 1), 256>>>(
        p_x, NQ, fw, fb, nullptr, out, 128, 128, 1);
}

// round 4
// speedup vs baseline: 1.6284x; 1.6284x over previous
#include <cuda_runtime.h>
#include <cuda_fp16.h>
#include <math.h>
#include <stdint.h>

#define NVOX 40000
#define NQ   8192
#define KK   96
#define C    128
#define FF   256
#define NH   8
#define DH   16
#define KVROW 136   // padded half stride for staged KV rows (272B = 17*16B)

// ---------------- scratch (device globals; no allocation) ----------------
__device__ float  g_kf[NVOX * C];          // LN(voxel_features)+key_pos, per voxel
__device__ __half g_KVh[NVOX * 2 * C];     // per-voxel [K(128) | V(128)] in fp16
__device__ float  g_qfeat[NQ * C];
__device__ float  g_q[NQ * C];
__device__ float  g_ctx[NQ * C];
__device__ float  g_att[NQ * C];
__device__ float  g_hn[NQ * C];
__device__ float  g_a1[NQ * FF];
__device__ float  g_x[NQ * C];

// ---------------- per-voxel LN + positional feature ----------------
__global__ void kf_kernel(const float* __restrict__ vf,
                          const float* __restrict__ vc,
                          const float* __restrict__ g1,
                          const float* __restrict__ b1,
                          const float* __restrict__ kpw,
                          const float* __restrict__ kpb)
{
    int v    = blockIdx.x * 8 + (threadIdx.x >> 5);
    int lane = threadIdx.x & 31;
    if (v >= NVOX) return;

    float4 x = ((const float4*)(vf + (size_t)v * C))[lane];
    float s = x.x + x.y + x.z + x.w;
    float q = x.x * x.x + x.y * x.y + x.z * x.z + x.w * x.w;
#pragma unroll
    for (int o = 16; o; o >>= 1) {
        s += __shfl_xor_sync(0xffffffffu, s, o);
        q += __shfl_xor_sync(0xffffffffu, q, o);
    }
    float m   = s * (1.0f / 128.0f);
    float var = q * (1.0f / 128.0f) - m * m;
    float r   = rsqrtf(var + 1e-5f);

    float cx = vc[v * 3 + 0], cy = vc[v * 3 + 1], cz = vc[v * 3 + 2];

    float o0[4];
    const float* xv = &x.x;
#pragma unroll
    for (int j = 0; j < 4; j++) {
        int c = lane * 4 + j;
        float y  = (xv[j] - m) * r * g1[c] + b1[c];
        float kp = fmaxf(kpw[c * 3 + 0] * cx + kpw[c * 3 + 1] * cy +
                         kpw[c * 3 + 2] * cz + kpb[c], 0.0f);
        o0[j] = y + kp;
    }
    ((float4*)(g_kf + (size_t)v * C))[lane] = make_float4(o0[0], o0[1], o0[2], o0[3]);
}

// ---------------- row LayerNorm (norm2) ----------------
__global__ void ln_kernel(const float* __restrict__ in,
                          const float* __restrict__ g,
                          const float* __restrict__ b,
                          float* __restrict__ out, int rows)
{
    int r    = blockIdx.x * 8 + (threadIdx.x >> 5);
    int lane = threadIdx.x & 31;
    if (r >= rows) return;

    float4 x = ((const float4*)(in + (size_t)r * C))[lane];
    float s = x.x + x.y + x.z + x.w;
    float q = x.x * x.x + x.y * x.y + x.z * x.z + x.w * x.w;
#pragma unroll
    for (int o = 16; o; o >>= 1) {
        s += __shfl_xor_sync(0xffffffffu, s, o);
        q += __shfl_xor_sync(0xffffffffu, q, o);
    }
    float m   = s * (1.0f / 128.0f);
    float var = q * (1.0f / 128.0f) - m * m;
    float rs  = rsqrtf(var + 1e-5f);

    float o0[4];
    const float* xv = &x.x;
#pragma unroll
    for (int j = 0; j < 4; j++) {
        int c = lane * 4 + j;
        o0[j] = (xv[j] - m) * rs * g[c] + b[c];
    }
    ((float4*)(out + (size_t)r * C))[lane] = make_float4(o0[0], o0[1], o0[2], o0[3]);
}

// ---------------- query positional feature ----------------
__global__ void qfeat_kernel(const float* __restrict__ qc,
                             const float* __restrict__ qpw,
                             const float* __restrict__ qpb)
{
    int t = blockIdx.x * 256 + threadIdx.x;
    int n = t >> 7, c = t & 127;
    float x = qc[n * 3 + 0], y = qc[n * 3 + 1], z = qc[n * 3 + 2];
    g_qfeat[t] = fmaxf(qpw[c * 3 + 0] * x + qpw[c * 3 + 1] * y +
                       qpw[c * 3 + 2] * z + qpb[c], 0.0f);
}

// ---------------- SGEMM 128x128 tile (used for the big NVOX KV projection) ----
// out[M,N] = A[M,Kd] @ W[N,Kd]^T + bias ; optional fp16 output
__global__ __launch_bounds__(256, 2)
void sgemm_kernel(const float* __restrict__ A, int M,
                  const float* __restrict__ W,
                  const float* __restrict__ bias,
                  void* __restrict__ out,
                  int N, int Kd, int halfout)
{
    __shared__ __align__(16) float As[2][8][132];
    __shared__ __align__(16) float Bs[2][8][132];

    const int tid  = threadIdx.x;
    const int m0   = blockIdx.x * 128;
    const int n0   = blockIdx.y * 128;
    const int warp = tid >> 5, lane = tid & 31;
    const int wm = warp >> 2, wn = warp & 3;
    const int lm = lane & 7,  ln = lane >> 3;

    const int lrow = tid >> 1;
    const int lk4  = (tid & 1) * 4;

    const bool arow_ok = (m0 + lrow) < M;
    const float* Ap = A + (size_t)(m0 + lrow) * Kd + lk4;
    const float* Wp = W + (size_t)(n0 + lrow) * Kd + lk4;

    float acc[8][8];
#pragma unroll
    for (int i = 0; i < 8; i++)
#pragma unroll
        for (int j = 0; j < 8; j++) acc[i][j] = 0.0f;

    float4 a4 = arow_ok ? *(const float4*)Ap : make_float4(0, 0, 0, 0);
    float4 b4 = *(const float4*)Wp;

    int buf = 0;
    As[0][lk4 + 0][lrow] = a4.x; As[0][lk4 + 1][lrow] = a4.y;
    As[0][lk4 + 2][lrow] = a4.z; As[0][lk4 + 3][lrow] = a4.w;
    Bs[0][lk4 + 0][lrow] = b4.x; Bs[0][lk4 + 1][lrow] = b4.y;
    Bs[0][lk4 + 2][lrow] = b4.z; Bs[0][lk4 + 3][lrow] = b4.w;
    __syncthreads();

    for (int kc = 0; kc < Kd; kc += 8) {
        const bool more = (kc + 8) < Kd;
        if (more) {
            a4 = arow_ok ? *(const float4*)(Ap + kc + 8) : make_float4(0, 0, 0, 0);
            b4 = *(const float4*)(Wp + kc + 8);
        }
#pragma unroll
        for (int k = 0; k < 8; k++) {
            float4 t0 = *(const float4*)&As[buf][k][wm * 64 + lm * 4];
            float4 t1 = *(const float4*)&As[buf][k][wm * 64 + lm * 4 + 32];
            float4 u0 = *(const float4*)&Bs[buf][k][wn * 32 + ln * 4];
            float4 u1 = *(const float4*)&Bs[buf][k][wn * 32 + ln * 4 + 16];
            float af[8] = {t0.x, t0.y, t0.z, t0.w, t1.x, t1.y, t1.z, t1.w};
            float bf[8] = {u0.x, u0.y, u0.z, u0.w, u1.x, u1.y, u1.z, u1.w};
#pragma unroll
            for (int i = 0; i < 8; i++)
#pragma unroll
                for (int j = 0; j < 8; j++) acc[i][j] += af[i] * bf[j];
        }
        if (more) {
            int nb = buf ^ 1;
            As[nb][lk4 + 0][lrow] = a4.x; As[nb][lk4 + 1][lrow] = a4.y;
            As[nb][lk4 + 2][lrow] = a4.z; As[nb][lk4 + 3][lrow] = a4.w;
            Bs[nb][lk4 + 0][lrow] = b4.x; Bs[nb][lk4 + 1][lrow] = b4.y;
            Bs[nb][lk4 + 2][lrow] = b4.z; Bs[nb][lk4 + 3][lrow] = b4.w;
            __syncthreads();
            buf = nb;
        }
    }

#pragma unroll
    for (int i = 0; i < 8; i++) {
        int mg = m0 + wm * 64 + lm * 4 + (i & 3) + ((i >> 2) * 32);
        if (mg >= M) continue;
#pragma unroll
        for (int j4 = 0; j4 < 2; j4++) {
            int ng = n0 + wn * 32 + ln * 4 + j4 * 16;
            float4 o;
            o.x = acc[i][j4 * 4 + 0] + bias[ng + 0];
            o.y = acc[i][j4 * 4 + 1] + bias[ng + 1];
            o.z = acc[i][j4 * 4 + 2] + bias[ng + 2];
            o.w = acc[i][j4 * 4 + 3] + bias[ng + 3];
            if (halfout) {
                __half* oh = (__half*)out + (size_t)mg * N + ng;
                *(__half2*)(oh + 0) = __floats2half2_rn(o.x, o.y);
                *(__half2*)(oh + 2) = __floats2half2_rn(o.z, o.w);
            } else {
                *(float4*)((float*)out + (size_t)mg * N + ng) = o;
            }
        }
    }
}

// ---------------- SGEMM 64x64 tile, 128 threads (query-side: many blocks) ----
// out[M,N] = A[M,Kd] @ W[N,Kd]^T + bias (+res)(relu). M,N multiples of 64.
__global__ __launch_bounds__(128)
void sgemm64_kernel(const float* __restrict__ A,
                    const float* __restrict__ W,
                    const float* __restrict__ bias,
                    const float* __restrict__ res,
                    float* __restrict__ out,
                    int N, int Kd, int dorelu)
{
    __shared__ __align__(16) float As[2][8][68];
    __shared__ __align__(16) float Bs[2][8][68];

    const int tid  = threadIdx.x;
    const int m0   = blockIdx.x * 64;
    const int n0   = blockIdx.y * 64;
    const int warp = tid >> 5, lane = tid & 31;
    const int wm = warp >> 1, wn = warp & 1;   // 2x2 warps of 32x32
    const int lm = lane >> 3, ln = lane & 7;   // 4 (x8 rows) x 8 (x4 cols)

    const int lrow = tid >> 1;        // 0..63
    const int lk4  = (tid & 1) * 4;

    const float* Ap = A + (size_t)(m0 + lrow) * Kd + lk4;
    const float* Wp = W + (size_t)(n0 + lrow) * Kd + lk4;

    float acc[8][4];
#pragma unroll
    for (int i = 0; i < 8; i++)
#pragma unroll
        for (int j = 0; j < 4; j++) acc[i][j] = 0.0f;

    float4 a4 = *(const float4*)Ap;
    float4 b4 = *(const float4*)Wp;

    int buf = 0;
    As[0][lk4 + 0][lrow] = a4.x; As[0][lk4 + 1][lrow] = a4.y;
    As[0][lk4 + 2][lrow] = a4.z; As[0][lk4 + 3][lrow] = a4.w;
    Bs[0][lk4 + 0][lrow] = b4.x; Bs[0][lk4 + 1][lrow] = b4.y;
    Bs[0][lk4 + 2][lrow] = b4.z; Bs[0][lk4 + 3][lrow] = b4.w;
    __syncthreads();

    for (int kc = 0; kc < Kd; kc += 8) {
        const bool more = (kc + 8) < Kd;
        if (more) {
            a4 = *(const float4*)(Ap + kc + 8);
            b4 = *(const float4*)(Wp + kc + 8);
        }
#pragma unroll
        for (int k = 0; k < 8; k++) {
            float4 a0 = *(const float4*)&As[buf][k][wm * 32 + lm * 8];
            float4 a1 = *(const float4*)&As[buf][k][wm * 32 + lm * 8 + 4];
            float4 b0 = *(const float4*)&Bs[buf][k][wn * 32 + ln * 4];
            float af[8] = {a0.x, a0.y, a0.z, a0.w, a1.x, a1.y, a1.z, a1.w};
            float bf[4] = {b0.x, b0.y, b0.z, b0.w};
#pragma unroll
            for (int i = 0; i < 8; i++)
#pragma unroll
                for (int j = 0; j < 4; j++) acc[i][j] += af[i] * bf[j];
        }
        if (more) {
            int nb = buf ^ 1;
            As[nb][lk4 + 0][lrow] = a4.x; As[nb][lk4 + 1][lrow] = a4.y;
            As[nb][lk4 + 2][lrow] = a4.z; As[nb][lk4 + 3][lrow] = a4.w;
            Bs[nb][lk4 + 0][lrow] = b4.x; Bs[nb][lk4 + 1][lrow] = b4.y;
            Bs[nb][lk4 + 2][lrow] = b4.z; Bs[nb][lk4 + 3][lrow] = b4.w;
            __syncthreads();
            buf = nb;
        }
    }

    const int ng = n0 + wn * 32 + ln * 4;
    float4 bi = *(const float4*)(bias + ng);
#pragma unroll
    for (int i = 0; i < 8; i++) {
        int mg = m0 + wm * 32 + lm * 8 + i;
        float4 o;
        o.x = acc[i][0] + bi.x;
        o.y = acc[i][1] + bi.y;
        o.z = acc[i][2] + bi.z;
        o.w = acc[i][3] + bi.w;
        if (res) {
            float4 rr = *(const float4*)(res + (size_t)mg * N + ng);
            o.x += rr.x; o.y += rr.y; o.z += rr.z; o.w += rr.w;
        }
        if (dorelu) {
            o.x = fmaxf(o.x, 0.0f); o.y = fmaxf(o.y, 0.0f);
            o.z = fmaxf(o.z, 0.0f); o.w = fmaxf(o.w, 0.0f);
        }
        *(float4*)(out + (size_t)mg * N + ng) = o;
    }
}

// ---------------- attention: one block per query, 128 threads ----------------
// KV staged through smem (zero-filled for masked keys); scores kept in regs.
__global__ __launch_bounds__(128)
void attn_kernel(const int* __restrict__ kidx)
{
    __shared__ int   idx_s[KK];
    __shared__ float qs[C];
    __shared__ float p_s[NH][KK];
    __shared__ __align__(16) __half kv_s[KK * KVROW];

    const int n = blockIdx.x;
    const int t = threadIdx.x;
    const int h = t >> 4, l16 = t & 15;

    if (t < KK) idx_s[t] = kidx[n * KK + t];
    qs[t] = g_q[(size_t)n * C + t];
    __syncthreads();

    // ---- stage K rows: 16 threads per row (256B), 8 rows per pass ----
    const int rg = t >> 4;     // row-in-group
    const int pp = t & 15;     // uint4 index within 256B
#pragma unroll
    for (int i = 0; i < 12; i++) {
        int k = i * 8 + rg;
        int v = idx_s[k];
        uint4 d = make_uint4(0, 0, 0, 0);
        if (v >= 0) d = ((const uint4*)(g_KVh + (size_t)v * 256))[pp];
        *(uint4*)(&kv_s[k * KVROW + pp * 8]) = d;
    }
    __syncthreads();

    // ---- scores: thread (h,l16) handles keys k = l16 + 16*m, all in regs ----
    float qreg[16];
#pragma unroll
    for (int d = 0; d < 16; d++) qreg[d] = qs[h * 16 + d];

    float sc[6];
#pragma unroll
    for (int m = 0; m < 6; m++) {
        int k = l16 + m * 16;
        const __half2* kp = (const __half2*)&kv_s[k * KVROW + h * 16];
        float s = 0.0f;
#pragma unroll
        for (int d = 0; d < 8; d++) {
            float2 kv2 = __half22float2(kp[d]);
            s += qreg[2 * d] * kv2.x + qreg[2 * d + 1] * kv2.y;
        }
        sc[m] = s * 0.25f;
    }

    // ---- softmax over valid keys (width-16 reductions) ----
    float mx = -1e30f;
#pragma unroll
    for (int m = 0; m < 6; m++)
        if (idx_s[l16 + m * 16] >= 0) mx = fmaxf(mx, sc[m]);
#pragma unroll
    for (int o = 8; o; o >>= 1)
        mx = fmaxf(mx, __shfl_xor_sync(0xffffffffu, mx, o, 16));

    float p[6];
    float sum = 0.0f;
#pragma unroll
    for (int m = 0; m < 6; m++) {
        p[m] = (idx_s[l16 + m * 16] >= 0) ? __expf(sc[m] - mx) : 0.0f;
        sum += p[m];
    }
#pragma unroll
    for (int o = 8; o; o >>= 1)
        sum += __shfl_xor_sync(0xffffffffu, sum, o, 16);
    const float inv = 1.0f / sum;
#pragma unroll
    for (int m = 0; m < 6; m++) p_s[h][l16 + m * 16] = p[m] * inv;
    __syncthreads();   // scores consumed; p_s written; kv_s free for V

    // ---- stage V rows (second 256B half of each KV row) ----
#pragma unroll
    for (int i = 0; i < 12; i++) {
        int k = i * 8 + rg;
        int v = idx_s[k];
        uint4 d = make_uint4(0, 0, 0, 0);
        if (v >= 0) d = ((const uint4*)(g_KVh + (size_t)v * 256))[16 + pp];
        *(uint4*)(&kv_s[k * KVROW + pp * 8]) = d;
    }
    __syncthreads();

    // ---- ctx[c] = sum_k p[h][k] * V[k][c]  (conflict-free: consecutive c) ----
    float acc = 0.0f;
#pragma unroll 8
    for (int k = 0; k < KK; k++)
        acc += p_s[h][k] * __half2float(kv_s[k * KVROW + t]);
    g_ctx[(size_t)n * C + t] = acc;
}

// ---------------- host launch ----------------
extern "C" void kernel_launch(void* const* d_in, const int* in_sizes, int n_in,
                              void* d_out, int out_size)
{
    const float* vf   = (const float*)d_in[0];
    const float* vc   = (const float*)d_in[1];
    const float* qc   = (const float*)d_in[2];
    const int*   kidx = (const int*)  d_in[3];
    const float* n1g  = (const float*)d_in[4];
    const float* n1b  = (const float*)d_in[5];
    const float* qpw  = (const float*)d_in[6];
    const float* qpb  = (const float*)d_in[7];
    const float* kpw  = (const float*)d_in[8];
    const float* kpb  = (const float*)d_in[9];
    const float* inw  = (const float*)d_in[10];
    const float* inb  = (const float*)d_in[11];
    const float* outw = (const float*)d_in[12];
    const float* outb = (const float*)d_in[13];
    const float* n2g  = (const float*)d_in[14];
    const float* n2b  = (const float*)d_in[15];
    const float* l1w  = (const float*)d_in[16];
    const float* l1b  = (const float*)d_in[17];
    const float* l2w  = (const float*)d_in[18];
    const float* l2b  = (const float*)d_in[19];
    const float* fw   = (const float*)d_in[20];
    const float* fb   = (const float*)d_in[21];
    float* out = (float*)d_out;

    float *p_kf, *p_qf, *p_q, *p_ctx, *p_att, *p_hn, *p_a1, *p_x;
    __half* p_KVh;
    cudaGetSymbolAddress((void**)&p_kf,  g_kf);
    cudaGetSymbolAddress((void**)&p_KVh, g_KVh);
    cudaGetSymbolAddress((void**)&p_qf,  g_qfeat);
    cudaGetSymbolAddress((void**)&p_q,   g_q);
    cudaGetSymbolAddress((void**)&p_ctx, g_ctx);
    cudaGetSymbolAddress((void**)&p_att, g_att);
    cudaGetSymbolAddress((void**)&p_hn,  g_hn);
    cudaGetSymbolAddress((void**)&p_a1,  g_a1);
    cudaGetSymbolAddress((void**)&p_x,   g_x);

    // 1) per-voxel LN + key positional feature
    kf_kernel<<<NVOX / 8, 256>>>(vf, vc, n1g, n1b, kpw, kpb);

    // 2) per-voxel K|V projection -> fp16 [NVOX,256]
    sgemm_kernel<<<dim3((NVOX + 127) / 128, 2), 256>>>(
        p_kf, NVOX, inw + 128 * 128, inb + 128, p_KVh, 256, 128, 1);

    // 3) query positional feature
    qfeat_kernel<<<(NQ * C) / 256, 256>>>(qc, qpw, qpb);

    // 4) q projection
    sgemm64_kernel<<<dim3(NQ / 64, 2), 128>>>(
        p_qf, inw, inb, nullptr, p_q, 128, 128, 0);

    // 5) sparse attention
    attn_kernel<<<NQ, 128>>>(kidx);

    // 6) output projection -> attend
    sgemm64_kernel<<<dim3(NQ / 64, 2), 128>>>(
        p_ctx, outw, outb, nullptr, p_att, 128, 128, 0);

    // 7) norm2
    ln_kernel<<<NQ / 8, 256>>>(p_att, n2g, n2b, p_hn, NQ);

    // 8) FFN up (relu)
    sgemm64_kernel<<<dim3(NQ / 64, 4), 128>>>(
        p_hn, l1w, l1b, nullptr, p_a1, 256, 128, 1);

    // 9) FFN down + residual(attend)
    sgemm64_kernel<<<dim3(NQ / 64, 2), 128>>>(
        p_a1, l2w, l2b, p_att, p_x, 128, 256, 0);

    // 10) final projection + relu -> output
    sgemm64_kernel<<<dim3(NQ / 64, 2), 128>>>(
        p_x, fw, fb, nullptr, out, 128, 128, 1);
}

// round 5
// speedup vs baseline: 1.8603x; 1.1424x over previous
#include <cuda_runtime.h>
#include <cuda_fp16.h>
#include <math.h>
#include <stdint.h>

#define NVOX 40000
#define NQ   8192
#define KK   96
#define C    128
#define FF   256
#define NH   8
#define DH   16
#define KVROW 136

// weight split buffer offsets (floats)
#define W_INW  0
#define W_OUTW 49152
#define W_L1W  65536
#define W_L2W  98304
#define W_FINW 131072
#define W_TOT  147456

// ---------------- scratch (device globals; no allocation) ----------------
__device__ float  g_kf_hi[NVOX * C],  g_kf_lo[NVOX * C];
__device__ __half g_KVh[NVOX * 2 * C];
__device__ float  g_qf_hi[NQ * C],    g_qf_lo[NQ * C];
__device__ float  g_q[NQ * C];
__device__ float  g_ctx_hi[NQ * C],   g_ctx_lo[NQ * C];
__device__ float  g_att[NQ * C];
__device__ float  g_hn_hi[NQ * C],    g_hn_lo[NQ * C];
__device__ float  g_a1_hi[NQ * FF],   g_a1_lo[NQ * FF];
__device__ float  g_x_hi[NQ * C],     g_x_lo[NQ * C];
__device__ float  g_w_hi[W_TOT],      g_w_lo[W_TOT];

// ---------------- helpers ----------------
__device__ __forceinline__ float tf32r(float x) {
    uint32_t u;
    asm("cvt.rna.tf32.f32 %0, %1;" : "=r"(u) : "f"(x));
    return __uint_as_float(u);
}

__device__ __forceinline__ void mma8(float* d, const float* a, const float* b) {
    asm volatile(
        "mma.sync.aligned.m16n8k8.row.col.f32.tf32.tf32.f32 "
        "{%0,%1,%2,%3}, {%4,%5,%6,%7}, {%8,%9}, {%0,%1,%2,%3};"
        : "+f"(d[0]), "+f"(d[1]), "+f"(d[2]), "+f"(d[3])
        : "r"(__float_as_uint(a[0])), "r"(__float_as_uint(a[1])),
          "r"(__float_as_uint(a[2])), "r"(__float_as_uint(a[3])),
          "r"(__float_as_uint(b[0])), "r"(__float_as_uint(b[1])));
}

// ---------------- weight hi/lo split (all 5 weight matrices, one launch) ----
__global__ void wsplit_kernel(const float* __restrict__ s0,  // in_w   49152
                              const float* __restrict__ s1,  // out_w  16384
                              const float* __restrict__ s2,  // lin1_w 32768
                              const float* __restrict__ s3,  // lin2_w 32768
                              const float* __restrict__ s4)  // fin_w  16384
{
    int i = blockIdx.x * 256 + threadIdx.x;
    if (i >= W_TOT) return;
    const float* s; int off;
    if      (i < W_OUTW) { s = s0; off = W_INW;  }
    else if (i < W_L1W)  { s = s1; off = W_OUTW; }
    else if (i < W_L2W)  { s = s2; off = W_L1W;  }
    else if (i < W_FINW) { s = s3; off = W_L2W;  }
    else                 { s = s4; off = W_FINW; }
    float x = s[i - off];
    float h = tf32r(x);
    g_w_hi[i] = h;
    g_w_lo[i] = tf32r(x - h);
}

// ---------------- per-voxel LN + positional feature -> hi/lo ----------------
__global__ void kf_kernel(const float* __restrict__ vf,
                          const float* __restrict__ vc,
                          const float* __restrict__ g1,
                          const float* __restrict__ b1,
                          const float* __restrict__ kpw,
                          const float* __restrict__ kpb)
{
    int v    = blockIdx.x * 8 + (threadIdx.x >> 5);
    int lane = threadIdx.x & 31;
    if (v >= NVOX) return;

    float4 x = ((const float4*)(vf + (size_t)v * C))[lane];
    float s = x.x + x.y + x.z + x.w;
    float q = x.x * x.x + x.y * x.y + x.z * x.z + x.w * x.w;
#pragma unroll
    for (int o = 16; o; o >>= 1) {
        s += __shfl_xor_sync(0xffffffffu, s, o);
        q += __shfl_xor_sync(0xffffffffu, q, o);
    }
    float m   = s * (1.0f / 128.0f);
    float var = q * (1.0f / 128.0f) - m * m;
    float r   = rsqrtf(var + 1e-5f);

    float cx = vc[v * 3 + 0], cy = vc[v * 3 + 1], cz = vc[v * 3 + 2];

    float hi[4], lo[4];
    const float* xv = &x.x;
#pragma unroll
    for (int j = 0; j < 4; j++) {
        int c = lane * 4 + j;
        float y  = (xv[j] - m) * r * g1[c] + b1[c];
        float kp = fmaxf(kpw[c * 3 + 0] * cx + kpw[c * 3 + 1] * cy +
                         kpw[c * 3 + 2] * cz + kpb[c], 0.0f);
        float t = y + kp;
        hi[j] = tf32r(t);
        lo[j] = tf32r(t - hi[j]);
    }
    ((float4*)(g_kf_hi + (size_t)v * C))[lane] = make_float4(hi[0], hi[1], hi[2], hi[3]);
    ((float4*)(g_kf_lo + (size_t)v * C))[lane] = make_float4(lo[0], lo[1], lo[2], lo[3]);
}

// ---------------- row LayerNorm (norm2) -> hi/lo ----------------
__global__ void ln_kernel(const float* __restrict__ in,
                          const float* __restrict__ g,
                          const float* __restrict__ b)
{
    int r    = blockIdx.x * 8 + (threadIdx.x >> 5);
    int lane = threadIdx.x & 31;

    float4 x = ((const float4*)(in + (size_t)r * C))[lane];
    float s = x.x + x.y + x.z + x.w;
    float q = x.x * x.x + x.y * x.y + x.z * x.z + x.w * x.w;
#pragma unroll
    for (int o = 16; o; o >>= 1) {
        s += __shfl_xor_sync(0xffffffffu, s, o);
        q += __shfl_xor_sync(0xffffffffu, q, o);
    }
    float m   = s * (1.0f / 128.0f);
    float var = q * (1.0f / 128.0f) - m * m;
    float rs  = rsqrtf(var + 1e-5f);

    float hi[4], lo[4];
    const float* xv = &x.x;
#pragma unroll
    for (int j = 0; j < 4; j++) {
        int c = lane * 4 + j;
        float t = (xv[j] - m) * rs * g[c] + b[c];
        hi[j] = tf32r(t);
        lo[j] = tf32r(t - hi[j]);
    }
    ((float4*)(g_hn_hi + (size_t)r * C))[lane] = make_float4(hi[0], hi[1], hi[2], hi[3]);
    ((float4*)(g_hn_lo + (size_t)r * C))[lane] = make_float4(lo[0], lo[1], lo[2], lo[3]);
}

// ---------------- query positional feature -> hi/lo ----------------
__global__ void qfeat_kernel(const float* __restrict__ qc,
                             const float* __restrict__ qpw,
                             const float* __restrict__ qpb)
{
    int t = blockIdx.x * 256 + threadIdx.x;
    int n = t >> 7, c = t & 127;
    float x = qc[n * 3 + 0], y = qc[n * 3 + 1], z = qc[n * 3 + 2];
    float v = fmaxf(qpw[c * 3 + 0] * x + qpw[c * 3 + 1] * y +
                    qpw[c * 3 + 2] * z + qpb[c], 0.0f);
    float h = tf32r(v);
    g_qf_hi[t] = h;
    g_qf_lo[t] = tf32r(v - h);
}

// ---------------- tensor-core GEMM (3xTF32) ----------------
// out[M,N] = A[M,Kd] @ W[N,Kd]^T (+bias)(+res)(relu)
// A,W supplied pre-split as (hi, lo). CTA tile 64x64, 4 warps of 32x32.
// flags: 1=relu, 2=res, 4=half out, 8=f32 out, 16=hi/lo out
__global__ __launch_bounds__(128)
void mma_gemm(const float* __restrict__ Ahi, const float* __restrict__ Alo,
              const float* __restrict__ Whi, const float* __restrict__ Wlo,
              const float* __restrict__ bias, const float* __restrict__ res,
              float* __restrict__ out32, __half* __restrict__ outh,
              float* __restrict__ ohi, float* __restrict__ olo,
              int N, int Kd, int flags)
{
    __shared__ float As[2][64][36];   // [hi/lo][row][k], pad 36 (banks 4r+c: conflict-free)
    __shared__ float Bs[2][64][36];

    const int tid = threadIdx.x;
    const int m0  = blockIdx.x * 64;
    const int n0  = blockIdx.y * 64;
    const int lane = tid & 31;
    const int g   = lane >> 2;       // 0..7
    const int tig = lane & 3;        // 0..3
    const int wm  = tid >> 6;        // 0..1
    const int wn  = (tid >> 5) & 1;  // 0..1

    const int lr  = tid >> 3;        // 0..15  (global-load row base)
    const int kq4 = (tid & 7) * 4;   // 0,4,..28

    float acc[2][4][4];
#pragma unroll
    for (int t = 0; t < 2; t++)
#pragma unroll
        for (int j = 0; j < 4; j++)
#pragma unroll
            for (int e = 0; e < 4; e++) acc[t][j][e] = 0.0f;

    float4 ra0[4], ra1[4], rb0[4], rb1[4];
#pragma unroll
    for (int i = 0; i < 4; i++) {
        size_t ao = (size_t)(m0 + lr + i * 16) * Kd + kq4;
        size_t bo = (size_t)(n0 + lr + i * 16) * Kd + kq4;
        ra0[i] = *(const float4*)(Ahi + ao);
        ra1[i] = *(const float4*)(Alo + ao);
        rb0[i] = *(const float4*)(Whi + bo);
        rb1[i] = *(const float4*)(Wlo + bo);
    }

    for (int kc = 0; kc < Kd; kc += 32) {
#pragma unroll
        for (int i = 0; i < 4; i++) {
            *(float4*)&As[0][lr + i * 16][kq4] = ra0[i];
            *(float4*)&As[1][lr + i * 16][kq4] = ra1[i];
            *(float4*)&Bs[0][lr + i * 16][kq4] = rb0[i];
            *(float4*)&Bs[1][lr + i * 16][kq4] = rb1[i];
        }
        __syncthreads();

        const bool more = (kc + 32) < Kd;
        if (more) {
#pragma unroll
            for (int i = 0; i < 4; i++) {
                size_t ao = (size_t)(m0 + lr + i * 16) * Kd + kc + 32 + kq4;
                size_t bo = (size_t)(n0 + lr + i * 16) * Kd + kc + 32 + kq4;
                ra0[i] = *(const float4*)(Ahi + ao);
                ra1[i] = *(const float4*)(Alo + ao);
                rb0[i] = *(const float4*)(Whi + bo);
                rb1[i] = *(const float4*)(Wlo + bo);
            }
        }

#pragma unroll
        for (int kk = 0; kk < 4; kk++) {
            const int k0 = kk * 8;
            float ah[2][4], al[2][4];
#pragma unroll
            for (int t = 0; t < 2; t++) {
                int r = wm * 32 + t * 16 + g;
                ah[t][0] = As[0][r][k0 + tig];
                ah[t][1] = As[0][r + 8][k0 + tig];
                ah[t][2] = As[0][r][k0 + tig + 4];
                ah[t][3] = As[0][r + 8][k0 + tig + 4];
                al[t][0] = As[1][r][k0 + tig];
                al[t][1] = As[1][r + 8][k0 + tig];
                al[t][2] = As[1][r][k0 + tig + 4];
                al[t][3] = As[1][r + 8][k0 + tig + 4];
            }
            float bh[4][2], bl[4][2];
#pragma unroll
            for (int j = 0; j < 4; j++) {
                int rn = wn * 32 + j * 8 + g;
                bh[j][0] = Bs[0][rn][k0 + tig];
                bh[j][1] = Bs[0][rn][k0 + tig + 4];
                bl[j][0] = Bs[1][rn][k0 + tig];
                bl[j][1] = Bs[1][rn][k0 + tig + 4];
            }
#pragma unroll
            for (int t = 0; t < 2; t++)
#pragma unroll
                for (int j = 0; j < 4; j++) {
                    mma8(acc[t][j], ah[t], bh[j]);
                    mma8(acc[t][j], ah[t], bl[j]);
                    mma8(acc[t][j], al[t], bh[j]);
                }
        }
        __syncthreads();
    }

    // epilogue
#pragma unroll
    for (int t = 0; t < 2; t++) {
#pragma unroll
        for (int j = 0; j < 4; j++) {
            int row0 = m0 + wm * 32 + t * 16 + g;
            int col  = n0 + wn * 32 + j * 8 + 2 * tig;
            float2 bi = *(const float2*)(bias + col);
#pragma unroll
            for (int h2 = 0; h2 < 2; h2++) {
                int row = row0 + h2 * 8;
                float x0 = acc[t][j][h2 * 2 + 0] + bi.x;
                float x1 = acc[t][j][h2 * 2 + 1] + bi.y;
                size_t o = (size_t)row * N + col;
                if (flags & 2) {
                    float2 r2 = *(const float2*)(res + o);
                    x0 += r2.x; x1 += r2.y;
                }
                if (flags & 1) { x0 = fmaxf(x0, 0.0f); x1 = fmaxf(x1, 0.0f); }
                if (flags & 8)  *(float2*)(out32 + o) = make_float2(x0, x1);
                if (flags & 4)  *(__half2*)(outh + o) = __floats2half2_rn(x0, x1);
                if (flags & 16) {
                    float h0 = tf32r(x0), h1 = tf32r(x1);
                    *(float2*)(ohi + o) = make_float2(h0, h1);
                    *(float2*)(olo + o) = make_float2(tf32r(x0 - h0), tf32r(x1 - h1));
                }
            }
        }
    }
}

// ---------------- attention: one block per query, 128 threads ----------------
__global__ __launch_bounds__(128)
void attn_kernel(const int* __restrict__ kidx)
{
    __shared__ int   idx_s[KK];
    __shared__ float qs[C];
    __shared__ float p_s[NH][KK];
    __shared__ __align__(16) __half kv_s[KK * KVROW];

    const int n = blockIdx.x;
    const int t = threadIdx.x;
    const int h = t >> 4, l16 = t & 15;

    if (t < KK) idx_s[t] = kidx[n * KK + t];
    qs[t] = g_q[(size_t)n * C + t];
    __syncthreads();

    const int rg = t >> 4;
    const int pp = t & 15;
#pragma unroll
    for (int i = 0; i < 12; i++) {
        int k = i * 8 + rg;
        int v = idx_s[k];
        uint4 d = make_uint4(0, 0, 0, 0);
        if (v >= 0) d = ((const uint4*)(g_KVh + (size_t)v * 256))[pp];
        *(uint4*)(&kv_s[k * KVROW + pp * 8]) = d;
    }
    __syncthreads();

    float qreg[16];
#pragma unroll
    for (int d = 0; d < 16; d++) qreg[d] = qs[h * 16 + d];

    float sc[6];
#pragma unroll
    for (int m = 0; m < 6; m++) {
        int k = l16 + m * 16;
        const __half2* kp = (const __half2*)&kv_s[k * KVROW + h * 16];
        float s = 0.0f;
#pragma unroll
        for (int d = 0; d < 8; d++) {
            float2 kv2 = __half22float2(kp[d]);
            s += qreg[2 * d] * kv2.x + qreg[2 * d + 1] * kv2.y;
        }
        sc[m] = s * 0.25f;
    }

    float mx = -1e30f;
#pragma unroll
    for (int m = 0; m < 6; m++)
        if (idx_s[l16 + m * 16] >= 0) mx = fmaxf(mx, sc[m]);
#pragma unroll
    for (int o = 8; o; o >>= 1)
        mx = fmaxf(mx, __shfl_xor_sync(0xffffffffu, mx, o, 16));

    float p[6];
    float sum = 0.0f;
#pragma unroll
    for (int m = 0; m < 6; m++) {
        p[m] = (idx_s[l16 + m * 16] >= 0) ? __expf(sc[m] - mx) : 0.0f;
        sum += p[m];
    }
#pragma unroll
    for (int o = 8; o; o >>= 1)
        sum += __shfl_xor_sync(0xffffffffu, sum, o, 16);
    const float inv = 1.0f / sum;
#pragma unroll
    for (int m = 0; m < 6; m++) p_s[h][l16 + m * 16] = p[m] * inv;
    __syncthreads();

#pragma unroll
    for (int i = 0; i < 12; i++) {
        int k = i * 8 + rg;
        int v = idx_s[k];
        uint4 d = make_uint4(0, 0, 0, 0);
        if (v >= 0) d = ((const uint4*)(g_KVh + (size_t)v * 256))[16 + pp];
        *(uint4*)(&kv_s[k * KVROW + pp * 8]) = d;
    }
    __syncthreads();

    float acc = 0.0f;
#pragma unroll 8
    for (int k = 0; k < KK; k++)
        acc += p_s[h][k] * __half2float(kv_s[k * KVROW + t]);

    float hi = tf32r(acc);
    g_ctx_hi[(size_t)n * C + t] = hi;
    g_ctx_lo[(size_t)n * C + t] = tf32r(acc - hi);
}

// ---------------- host launch ----------------
extern "C" void kernel_launch(void* const* d_in, const int* in_sizes, int n_in,
                              void* d_out, int out_size)
{
    const float* vf   = (const float*)d_in[0];
    const float* vc   = (const float*)d_in[1];
    const float* qc   = (const float*)d_in[2];
    const int*   kidx = (const int*)  d_in[3];
    const float* n1g  = (const float*)d_in[4];
    const float* n1b  = (const float*)d_in[5];
    const float* qpw  = (const float*)d_in[6];
    const float* qpb  = (const float*)d_in[7];
    const float* kpw  = (const float*)d_in[8];
    const float* kpb  = (const float*)d_in[9];
    const float* inw  = (const float*)d_in[10];
    const float* inb  = (const float*)d_in[11];
    const float* outw = (const float*)d_in[12];
    const float* outb = (const float*)d_in[13];
    const float* n2g  = (const float*)d_in[14];
    const float* n2b  = (const float*)d_in[15];
    const float* l1w  = (const float*)d_in[16];
    const float* l1b  = (const float*)d_in[17];
    const float* l2w  = (const float*)d_in[18];
    const float* l2b  = (const float*)d_in[19];
    const float* fw   = (const float*)d_in[20];
    const float* fb   = (const float*)d_in[21];
    float* out = (float*)d_out;

    float *p_kf_hi, *p_kf_lo, *p_qf_hi, *p_qf_lo, *p_q, *p_ctx_hi, *p_ctx_lo;
    float *p_att, *p_hn_hi, *p_hn_lo, *p_a1_hi, *p_a1_lo, *p_x_hi, *p_x_lo;
    float *p_w_hi, *p_w_lo;
    __half* p_KVh;
    cudaGetSymbolAddress((void**)&p_kf_hi,  g_kf_hi);
    cudaGetSymbolAddress((void**)&p_kf_lo,  g_kf_lo);
    cudaGetSymbolAddress((void**)&p_KVh,    g_KVh);
    cudaGetSymbolAddress((void**)&p_qf_hi,  g_qf_hi);
    cudaGetSymbolAddress((void**)&p_qf_lo,  g_qf_lo);
    cudaGetSymbolAddress((void**)&p_q,      g_q);
    cudaGetSymbolAddress((void**)&p_ctx_hi, g_ctx_hi);
    cudaGetSymbolAddress((void**)&p_ctx_lo, g_ctx_lo);
    cudaGetSymbolAddress((void**)&p_att,    g_att);
    cudaGetSymbolAddress((void**)&p_hn_hi,  g_hn_hi);
    cudaGetSymbolAddress((void**)&p_hn_lo,  g_hn_lo);
    cudaGetSymbolAddress((void**)&p_a1_hi,  g_a1_hi);
    cudaGetSymbolAddress((void**)&p_a1_lo,  g_a1_lo);
    cudaGetSymbolAddress((void**)&p_x_hi,   g_x_hi);
    cudaGetSymbolAddress((void**)&p_x_lo,   g_x_lo);
    cudaGetSymbolAddress((void**)&p_w_hi,   g_w_hi);
    cudaGetSymbolAddress((void**)&p_w_lo,   g_w_lo);

    // 0) split all weights into tf32 hi/lo
    wsplit_kernel<<<(W_TOT + 255) / 256, 256>>>(inw, outw, l1w, l2w, fw);

    // 1) per-voxel LN + key positional feature (pre-split)
    kf_kernel<<<NVOX / 8, 256>>>(vf, vc, n1g, n1b, kpw, kpb);

    // 2) per-voxel K|V projection -> fp16 [NVOX,256]
    mma_gemm<<<dim3(NVOX / 64, 4), 128>>>(
        p_kf_hi, p_kf_lo, p_w_hi + W_INW + 128 * 128, p_w_lo + W_INW + 128 * 128,
        inb + 128, nullptr, nullptr, p_KVh, nullptr, nullptr, 256, 128, 4);

    // 3) query positional feature (pre-split)
    qfeat_kernel<<<(NQ * C) / 256, 256>>>(qc, qpw, qpb);

    // 4) q projection -> fp32
    mma_gemm<<<dim3(NQ / 64, 2), 128>>>(
        p_qf_hi, p_qf_lo, p_w_hi + W_INW, p_w_lo + W_INW,
        inb, nullptr, p_q, nullptr, nullptr, nullptr, 128, 128, 8);

    // 5) sparse attention -> ctx hi/lo
    attn_kernel<<<NQ, 128>>>(kidx);

    // 6) output projection -> attend fp32
    mma_gemm<<<dim3(NQ / 64, 2), 128>>>(
        p_ctx_hi, p_ctx_lo, p_w_hi + W_OUTW, p_w_lo + W_OUTW,
        outb, nullptr, p_att, nullptr, nullptr, nullptr, 128, 128, 8);

    // 7) norm2 -> hn hi/lo
    ln_kernel<<<NQ / 8, 256>>>(p_att, n2g, n2b);

    // 8) FFN up (relu) -> a1 hi/lo
    mma_gemm<<<dim3(NQ / 64, 4), 128>>>(
        p_hn_hi, p_hn_lo, p_w_hi + W_L1W, p_w_lo + W_L1W,
        l1b, nullptr, nullptr, nullptr, p_a1_hi, p_a1_lo, 256, 128, 16 | 1);

    // 9) FFN down + residual(attend) -> x hi/lo
    mma_gemm<<<dim3(NQ / 64, 2), 128>>>(
        p_a1_hi, p_a1_lo, p_w_hi + W_L2W, p_w_lo + W_L2W,
        l2b, p_att, nullptr, nullptr, p_x_hi, p_x_lo, 128, 256, 16 | 2);

    // 10) final projection + relu -> output fp32
    mma_gemm<<<dim3(NQ / 64, 2), 128>>>(
        p_x_hi, p_x_lo, p_w_hi + W_FINW, p_w_lo + W_FINW,
        fb, nullptr, out, nullptr, nullptr, nullptr, 128, 128, 8 | 1);
}